// round 15
// baseline (speedup 1.0000x reference)
#include <cuda_runtime.h>
#include <cuda_fp16.h>
#include <float.h>
#include <stdint.h>

#define HID 4096
#define SLOTS 8
#define HEADS 8
#define BD 512
#define HD 64
#define BB 4
#define SS 4096
#define NH 64   // HEADS*SLOTS

// Scratch (no allocations allowed)
__device__ float  g_Q[SLOTS * BD];
__device__ __half g_Qk16[NH * HID];              // fp16, scaled by 1/8
__device__ __half g_H16c[(size_t)BB * SS * HID]; // fp16 H, compacted rows
__device__ __half g_spart16[4 * BB * NH * SS];   // split-K score partials (fp16)
__device__ __half g_attnh[BB * NH * SS];         // attn probs (fp16)
__device__ __half g_apart16[2 * BB * NH * HID];  // split-s agg partials (fp16)
__device__ float  g_mid[BB * SLOTS * BD];
__device__ int    g_sidx[BB * SS];
__device__ int    g_cnt[BB];

#define SPART_SZ (BB * NH * SS)
#define APART_SZ (BB * NH * HID)

__device__ __forceinline__ void mma_f16(float* d, const uint32_t* a, const uint32_t* b) {
    asm volatile(
        "mma.sync.aligned.m16n8k16.row.col.f32.f16.f16.f32 "
        "{%0,%1,%2,%3}, {%4,%5,%6,%7}, {%8,%9}, {%0,%1,%2,%3};"
        : "+f"(d[0]), "+f"(d[1]), "+f"(d[2]), "+f"(d[3])
        : "r"(a[0]), "r"(a[1]), "r"(a[2]), "r"(a[3]), "r"(b[0]), "r"(b[1]));
}

__device__ __forceinline__ void ldm_x4(uint32_t* r, uint32_t addr) {
    asm volatile(
        "ldmatrix.sync.aligned.m8n8.x4.shared.b16 {%0,%1,%2,%3}, [%4];"
        : "=r"(r[0]), "=r"(r[1]), "=r"(r[2]), "=r"(r[3]) : "r"(addr));
}

__device__ __forceinline__ void ldm_x4t(uint32_t* r, uint32_t addr) {
    asm volatile(
        "ldmatrix.sync.aligned.m8n8.x4.trans.shared.b16 {%0,%1,%2,%3}, [%4];"
        : "=r"(r[0]), "=r"(r[1]), "=r"(r[2]), "=r"(r[3]) : "r"(addr));
}

__device__ __forceinline__ void cp16(uint32_t smem_dst, const void* gsrc) {
    asm volatile("cp.async.cg.shared.global [%0], [%1], 16;" :: "r"(smem_dst), "l"(gsrc));
}
#define CP_COMMIT asm volatile("cp.async.commit_group;")
#define CP_WAIT2  asm volatile("cp.async.wait_group 2;")
#define CP_WAIT0  asm volatile("cp.async.wait_group 0;")

// ---------------------------------------------------------------------------
// A) HORIZONTAL FUSION: blocks [0,BB) compact+zero g_mid; blocks [BB,..) qproj
__global__ void kA(const int* __restrict__ mask,
                   const float* __restrict__ ms, const float* __restrict__ Wq) {
    int tid = threadIdx.x;
    if (blockIdx.x < BB) {
        __shared__ int tsum[256];
        int b = blockIdx.x;
        const int* m = mask + b * SS;
        int loc[16], cnt = 0;
        #pragma unroll
        for (int k = 0; k < 16; k++) {
            loc[k] = (m[tid * 16 + k] != 0);
            cnt += loc[k];
        }
        tsum[tid] = cnt;
        __syncthreads();
        for (int o = 1; o < 256; o <<= 1) {
            int v = (tid >= o) ? tsum[tid - o] : 0;
            __syncthreads();
            tsum[tid] += v;
            __syncthreads();
        }
        int off = tsum[tid] - cnt;
        int total = tsum[255];
        int* out = g_sidx + b * SS;
        #pragma unroll
        for (int k = 0; k < 16; k++)
            if (loc[k]) out[off++] = tid * 16 + k;
        if (tid == 0) g_cnt[b] = total;
        float* gm = g_mid + b * 4096;
        #pragma unroll
        for (int k = 0; k < 16; k++) gm[k * 256 + tid] = 0.f;
    } else {
        int warp = ((blockIdx.x - BB) * 256 + tid) >> 5;
        int lane = tid & 31;
        if (warp >= SLOTS * BD) return;
        int n = warp / BD, c = warp % BD;
        const float* a = ms + n * HID;
        const float* w = Wq + c * HID;
        float acc = 0.f;
        for (int i = lane; i < HID; i += 32) acc += a[i] * w[i];
        #pragma unroll
        for (int off = 16; off; off >>= 1) acc += __shfl_down_sync(0xffffffffu, acc, off);
        if (lane == 0) g_Q[n * BD + c] = acc;
    }
}

// ---------------------------------------------------------------------------
// B) HORIZONTAL FUSION: blocks [0, BB*SS) conv (1 row/block, pad 128); rest qk
__global__ void kB(const float* __restrict__ H, const float* __restrict__ Wk) {
    cudaGridDependencySynchronize();
    int tid = threadIdx.x;
    int blk = blockIdx.x;
    if (blk < BB * SS) {
        int b = blk >> 12, cs = blk & 4095;
        int cnt = g_cnt[b];
        if (cs < cnt) {
            int s = g_sidx[b * SS + cs];
            const float4* src = (const float4*)(H + ((size_t)b * SS + s) * HID);
            uint2* dst = (uint2*)(g_H16c + ((size_t)b * SS + cs) * HID);
            float4 v0 = src[tid];
            float4 v1 = src[256 + tid];
            float4 v2 = src[512 + tid];
            float4 v3 = src[768 + tid];
            __half2 a0 = __floats2half2_rn(v0.x, v0.y), a1 = __floats2half2_rn(v0.z, v0.w);
            __half2 b0 = __floats2half2_rn(v1.x, v1.y), b1 = __floats2half2_rn(v1.z, v1.w);
            __half2 c0 = __floats2half2_rn(v2.x, v2.y), c1 = __floats2half2_rn(v2.z, v2.w);
            __half2 d0 = __floats2half2_rn(v3.x, v3.y), d1 = __floats2half2_rn(v3.z, v3.w);
            uint2 p0 = make_uint2(*(uint32_t*)&a0, *(uint32_t*)&a1);
            uint2 p1 = make_uint2(*(uint32_t*)&b0, *(uint32_t*)&b1);
            uint2 p2 = make_uint2(*(uint32_t*)&c0, *(uint32_t*)&c1);
            uint2 p3 = make_uint2(*(uint32_t*)&d0, *(uint32_t*)&d1);
            dst[tid] = p0; dst[256 + tid] = p1; dst[512 + tid] = p2; dst[768 + tid] = p3;
        } else if (cs < cnt + 128) {
            uint2* dst = (uint2*)(g_H16c + ((size_t)b * SS + cs) * HID);
            uint2 z = make_uint2(0u, 0u);
            dst[tid] = z; dst[256 + tid] = z; dst[512 + tid] = z; dst[768 + tid] = z;
        }
    } else {
        __shared__ float qs[HD];
        int idx = blk - BB * SS;
        int j = idx >> 4;            // 0..63
        int chunk = idx & 15;
        int h = j >> 3, n = j & 7;
        if (tid < HD) qs[tid] = g_Q[n * BD + h * HD + tid];
        __syncthreads();
        int i = chunk * 256 + tid;
        float acc = 0.f;
        #pragma unroll 8
        for (int d = 0; d < HD; d++) acc += qs[d] * Wk[(h * HD + d) * HID + i];
        g_Qk16[j * HID + i] = __float2half(acc * 0.125f);
    }
}

// ---------------------------------------------------------------------------
// 3) scores fp16: tile 128cs x 64j, split-K x4, 4-stage cp.async, ldmatrix
#define SC_A_B (128 * 80)           // 10240 B
#define SC_B_B (64 * 80)            // 5120 B
#define SC_STAGE_B (SC_A_B + SC_B_B)// 15360 B
__global__ void __launch_bounds__(256) k_scores() {
    cudaGridDependencySynchronize();
    extern __shared__ char smc[];
    int b = blockIdx.y, m0 = blockIdx.x * 128, kc = blockIdx.z;
    int cnt = g_cnt[b];
    if (m0 >= cnt) return;
    int tid = threadIdx.x, lane = tid & 31, w = tid >> 5;
    int wm = w & 3, wn = w >> 2;       // 4 m-groups x 2 n-groups
    int R = wm * 32, C = wn * 32;
    int ar = lane >> 2, ac = lane & 3;
    uint32_t smem_u32 = (uint32_t)__cvta_generic_to_shared(smc);

    float acc[2][4][4];
    #pragma unroll
    for (int t = 0; t < 2; t++)
        #pragma unroll
        for (int n = 0; n < 4; n++)
            #pragma unroll
            for (int q = 0; q < 4; q++) acc[t][n][q] = 0.f;

    int arow = tid >> 2;               // 0..63
    int aseg = tid & 3;                // 0..3 x16B
    const __half* Asrc = g_H16c + ((size_t)b * SS + m0) * HID + kc * 1024;
    const __half* Bsrc = g_Qk16 + kc * 1024;

    auto issue = [&](int stage, int it) {
        int st = it * 32;
        uint32_t base = smem_u32 + stage * SC_STAGE_B;
        cp16(base + arow * 80 + aseg * 16, Asrc + (size_t)arow * HID + st + aseg * 8);
        cp16(base + (arow + 64) * 80 + aseg * 16,
             Asrc + (size_t)(arow + 64) * HID + st + aseg * 8);
        cp16(base + SC_A_B + arow * 80 + aseg * 16,
             Bsrc + (size_t)arow * HID + st + aseg * 8);
    };

    int lr16 = lane & 15;
    int lhi = lane >> 4;

    const int NIT = 32;
    issue(0, 0); CP_COMMIT;
    issue(1, 1); CP_COMMIT;
    issue(2, 2); CP_COMMIT;
    for (int it = 0; it < NIT; it++) {
        CP_WAIT2;
        __syncthreads();
        if (it + 3 < NIT) issue((it + 3) & 3, it + 3);
        CP_COMMIT;
        uint32_t abase = smem_u32 + (it & 3) * SC_STAGE_B;
        uint32_t bbase = abase + SC_A_B;
        #pragma unroll
        for (int ks = 0; ks < 2; ks++) {
            uint32_t colb = (uint32_t)(ks * 32 + lhi * 16);
            uint32_t a[2][4];
            #pragma unroll
            for (int t = 0; t < 2; t++)
                ldm_x4(a[t], abase + (uint32_t)((R + t * 16 + lr16) * 80) + colb);
            uint32_t rbA[4], rbB[4];
            ldm_x4(rbA, bbase + (uint32_t)((C + lr16) * 80) + colb);
            ldm_x4(rbB, bbase + (uint32_t)((C + 16 + lr16) * 80) + colb);
            uint32_t bf[4][2] = {{rbA[0], rbA[2]}, {rbA[1], rbA[3]},
                                 {rbB[0], rbB[2]}, {rbB[1], rbB[3]}};
            #pragma unroll
            for (int t = 0; t < 2; t++)
                #pragma unroll
                for (int n = 0; n < 4; n++)
                    mma_f16(acc[t][n], a[t], bf[n]);
        }
    }
    CP_WAIT0;
    __syncthreads();

    // transpose-stage C (128cs x 64j) -> g_spart16[kc][(b,j)][cs]
    float* Cs = (float*)smc;
    #pragma unroll
    for (int t = 0; t < 2; t++) {
        #pragma unroll
        for (int n = 0; n < 4; n++) {
            int row = R + t * 16 + ar;
            int col = C + n * 8 + 2 * ac;
            Cs[col * 130 + row]            = acc[t][n][0];
            Cs[(col + 1) * 130 + row]      = acc[t][n][1];
            Cs[col * 130 + row + 8]        = acc[t][n][2];
            Cs[(col + 1) * 130 + row + 8]  = acc[t][n][3];
        }
    }
    __syncthreads();
    __half* dst = g_spart16 + (size_t)kc * SPART_SZ;
    #pragma unroll
    for (int l = 0; l < 32; l++) {
        int e = l * 256 + tid;
        int j = e >> 7, m = e & 127;
        dst[((b * NH + j) << 12) + m0 + m] = __float2half(Cs[j * 130 + m]);
    }
}

// ---------------------------------------------------------------------------
// 4) softmax (1024 threads): sum 4 fp16 split-K partials, softmax -> fp16
__global__ void __launch_bounds__(1024) k_softmax() {
    cudaGridDependencySynchronize();
    __shared__ float red[1024];
    int row = blockIdx.x;
    int b = row >> 6;
    int cnt = g_cnt[b];
    const __half* p0 = g_spart16 + (size_t)row * SS;
    __half* sc = g_attnh + (size_t)row * SS;
    int tid = threadIdx.x;
    float v[4];
    float mx = -FLT_MAX;
    #pragma unroll
    for (int k = 0; k < 4; k++) {
        int s = k * 1024 + tid;
        float val = -FLT_MAX;
        if (s < cnt)
            val = __half2float(p0[s]) + __half2float(p0[SPART_SZ + s])
                + __half2float(p0[2 * SPART_SZ + s]) + __half2float(p0[3 * SPART_SZ + s]);
        v[k] = val;
        mx = fmaxf(mx, val);
    }
    red[tid] = mx; __syncthreads();
    for (int o = 512; o; o >>= 1) { if (tid < o) red[tid] = fmaxf(red[tid], red[tid + o]); __syncthreads(); }
    mx = red[0]; __syncthreads();
    float sum = 0.f;
    #pragma unroll
    for (int k = 0; k < 4; k++) {
        int s = k * 1024 + tid;
        v[k] = (s < cnt) ? __expf(v[k] - mx) : 0.f;
        sum += v[k];
    }
    red[tid] = sum; __syncthreads();
    for (int o = 512; o; o >>= 1) { if (tid < o) red[tid] += red[tid + o]; __syncthreads(); }
    float inv = 1.f / red[0];
    #pragma unroll
    for (int k = 0; k < 4; k++) sc[k * 1024 + tid] = __float2half(v[k] * inv);
}

// ---------------------------------------------------------------------------
// 5) agg fp16: tile 64j x 128i, split-s x2, A via ldmatrix.x4,
//    B=H16c [s][i] via ldmatrix.x4.trans; fp16 partial output
#define AGA_B (64 * 80)              // 5120 B attn tile
#define AGB_STRIDE 272               // B row stride bytes (128 halves + 8 pad)
#define AGB_B (32 * AGB_STRIDE)      // 8704 B
#define AG_STAGE_B (AGA_B + AGB_B)   // 13824 B
__global__ void __launch_bounds__(256) k_agg() {
    cudaGridDependencySynchronize();
    extern __shared__ char smc[];
    int tid = threadIdx.x, lane = tid & 31, w = tid >> 5;
    int wm = w & 1, wn = w >> 1;       // 2 j-groups x 4 i-groups
    int R = wm * 32, C = wn * 32;
    int b = blockIdx.y;
    int i0 = blockIdx.x * 128;
    int sc_id = blockIdx.z;
    int ar = lane >> 2, ac = lane & 3;
    int cnt = g_cnt[b];
    int NIT_total = (cnt + 31) >> 5;
    int half = (NIT_total + 1) >> 1;
    int it0 = sc_id * half;
    int it1 = min(NIT_total, it0 + half);

    uint32_t smem_u32 = (uint32_t)__cvta_generic_to_shared(smc);

    float acc[2][4][4];
    #pragma unroll
    for (int t = 0; t < 2; t++)
        #pragma unroll
        for (int n = 0; n < 4; n++)
            #pragma unroll
            for (int q = 0; q < 4; q++) acc[t][n][q] = 0.f;

    const __half* Asrc = g_attnh + (size_t)b * NH * SS;
    const __half* Bsrc = g_H16c + (size_t)b * SS * HID + i0;

    int rrow = tid >> 2;               // 0..63 (attn rows)
    int rc8 = (tid & 3) * 8;
    int brow = tid >> 3;               // 0..31 (H rows)
    int bseg = tid & 7;                // 0..7

    auto issue = [&](int stage, int it) {
        int st = it * 32;
        uint32_t base = smem_u32 + stage * AG_STAGE_B;
        cp16(base + rrow * 80 + (tid & 3) * 16, Asrc + (size_t)rrow * SS + st + rc8);
        uint32_t bb = base + AGA_B + brow * AGB_STRIDE;
        const __half* hb = Bsrc + (size_t)(st + brow) * HID;
        cp16(bb + bseg * 16, hb + bseg * 8);
        cp16(bb + (bseg + 8) * 16, hb + (bseg + 8) * 8);
    };

    int lr16 = lane & 15;
    int lhi = lane >> 4;

    if (it0 < it1) {
        issue(0, it0); CP_COMMIT;
        if (it0 + 1 < it1) issue(1, it0 + 1); CP_COMMIT;
        if (it0 + 2 < it1) issue(2, it0 + 2); CP_COMMIT;
        for (int it = it0; it < it1; it++) {
            CP_WAIT2;
            __syncthreads();
            if (it + 3 < it1) issue((it - it0 + 3) & 3, it + 3);
            CP_COMMIT;
            int stg = (it - it0) & 3;
            uint32_t abase = smem_u32 + stg * AG_STAGE_B;
            uint32_t bbase = abase + AGA_B;
            #pragma unroll
            for (int ks = 0; ks < 2; ks++) {
                uint32_t colb = (uint32_t)(ks * 32 + lhi * 16);
                uint32_t a[2][4];
                #pragma unroll
                for (int t = 0; t < 2; t++)
                    ldm_x4(a[t], abase + (uint32_t)((R + t * 16 + lr16) * 80) + colb);
                uint32_t rowb = (uint32_t)((ks * 16 + lr16) * AGB_STRIDE);
                uint32_t rb0[4], rb1[4];
                ldm_x4t(rb0, bbase + rowb + (uint32_t)((C + lhi * 8) * 2));
                ldm_x4t(rb1, bbase + rowb + (uint32_t)((C + 16 + lhi * 8) * 2));
                uint32_t bf[4][2] = {{rb0[0], rb0[1]}, {rb0[2], rb0[3]},
                                     {rb1[0], rb1[1]}, {rb1[2], rb1[3]}};
                #pragma unroll
                for (int t = 0; t < 2; t++)
                    #pragma unroll
                    for (int n = 0; n < 4; n++)
                        mma_f16(acc[t][n], a[t], bf[n]);
            }
        }
    }

    __half* dst = g_apart16 + (size_t)sc_id * APART_SZ;
    #pragma unroll
    for (int t = 0; t < 2; t++) {
        #pragma unroll
        for (int n = 0; n < 4; n++) {
            int j = R + t * 16 + ar;
            int i = C + n * 8 + 2 * ac;
            __half2 h0 = __floats2half2_rn(acc[t][n][0], acc[t][n][1]);
            __half2 h1 = __floats2half2_rn(acc[t][n][2], acc[t][n][3]);
            *(__half2*)&dst[(size_t)(b * NH + j) * HID + i0 + i]     = h0;
            *(__half2*)&dst[(size_t)(b * NH + j + 8) * HID + i0 + i] = h1;
        }
    }
}

// ---------------------------------------------------------------------------
// 6) mid, split-K x4 with atomic epilogue; sums the 2 fp16 agg partials
__global__ void k_mid(const float* __restrict__ Wv) {
    cudaGridDependencySynchronize();
    __shared__ float As[8][65];
    __shared__ float Bs[64][65];
    int h = blockIdx.x, b = blockIdx.y, kc = blockIdx.z;
    int tid = threadIdx.x;
    float acc0 = 0.f, acc1 = 0.f;
    int o0 = tid, o1 = tid + 256;
    int n0 = o0 >> 6, d0 = o0 & 63;
    int n1 = o1 >> 6, d1 = o1 & 63;
    int k0 = kc * (HID / 4), k1 = k0 + HID / 4;
    for (int kt = k0; kt < k1; kt += 64) {
        {
            int e = tid; int r = e >> 6, c = e & 63;
            size_t ix = (size_t)(b * NH + h * SLOTS + r) * HID + kt + c;
            As[r][c] = __half2float(g_apart16[ix]) + __half2float(g_apart16[APART_SZ + ix]);
            e = tid + 256; r = e >> 6; c = e & 63;
            ix = (size_t)(b * NH + h * SLOTS + r) * HID + kt + c;
            As[r][c] = __half2float(g_apart16[ix]) + __half2float(g_apart16[APART_SZ + ix]);
        }
        #pragma unroll
        for (int l = 0; l < 16; l++) {
            int e = tid + l * 256;
            int r = e >> 6, c = e & 63;
            Bs[r][c] = Wv[(h * HD + r) * HID + kt + c];
        }
        __syncthreads();
        #pragma unroll
        for (int k = 0; k < 64; k++) {
            acc0 += As[n0][k] * Bs[d0][k];
            acc1 += As[n1][k] * Bs[d1][k];
        }
        __syncthreads();
    }
    atomicAdd(&g_mid[(b * SLOTS + n0) * BD + h * HD + d0], acc0);
    atomicAdd(&g_mid[(b * SLOTS + n1) * BD + h * HD + d1], acc1);
}

// ---------------------------------------------------------------------------
// 7) final, o-tile 64, 512 threads
__global__ void __launch_bounds__(512) k_final(const float* __restrict__ Wo,
                                               float* __restrict__ out) {
    cudaGridDependencySynchronize();
    __shared__ float As[32][65];
    __shared__ float Bs[64][65];
    int tid = threadIdx.x;
    int tx = tid & 15, ty = tid >> 4;      // 16 col-groups x 32 rows
    int o0 = blockIdx.x * 64;
    float acc[4] = {};
    for (int kt = 0; kt < BD; kt += 64) {
        #pragma unroll
        for (int l = 0; l < 4; l++) {
            int e = tid + l * 512;
            int r = e >> 6, c = e & 63;
            As[r][c] = g_mid[r * BD + kt + c];
        }
        #pragma unroll
        for (int l = 0; l < 8; l++) {
            int e = tid + l * 512;
            int r = e >> 6, c = e & 63;
            Bs[r][c] = Wo[(o0 + r) * BD + kt + c];
        }
        __syncthreads();
        #pragma unroll
        for (int k = 0; k < 64; k++) {
            float a = As[ty][k];
            #pragma unroll
            for (int y = 0; y < 4; y++) acc[y] += a * Bs[tx * 4 + y][k];
        }
        __syncthreads();
    }
    #pragma unroll
    for (int y = 0; y < 4; y++)
        out[ty * HID + o0 + tx * 4 + y] = acc[y];
}

// ---------------------------------------------------------------------------
template <typename K, typename... Args>
static void launch_pdl(K kern, dim3 grid, dim3 block, size_t smem, Args... args) {
    cudaLaunchConfig_t cfg = {};
    cfg.gridDim = grid;
    cfg.blockDim = block;
    cfg.dynamicSmemBytes = smem;
    cudaLaunchAttribute at[1];
    at[0].id = cudaLaunchAttributeProgrammaticStreamSerialization;
    at[0].val.programmaticStreamSerializationAllowed = 1;
    cfg.attrs = at;
    cfg.numAttrs = 1;
    cudaLaunchKernelEx(&cfg, kern, args...);
}

extern "C" void kernel_launch(void* const* d_in, const int* in_sizes, int n_in,
                              void* d_out, int out_size) {
    const float* H    = (const float*)d_in[0];
    const int*   mask = (const int*)d_in[1];
    const float* ms   = (const float*)d_in[2];
    const float* Wq   = (const float*)d_in[3];
    const float* Wk   = (const float*)d_in[4];
    const float* Wv   = (const float*)d_in[5];
    const float* Wo   = (const float*)d_in[6];
    float* out = (float*)d_out;

    static int attr_done = 0;
    if (!attr_done) {
        cudaFuncSetAttribute(k_scores, cudaFuncAttributeMaxDynamicSharedMemorySize,
                             4 * SC_STAGE_B);
        cudaFuncSetAttribute(k_agg, cudaFuncAttributeMaxDynamicSharedMemorySize,
                             4 * AG_STAGE_B);
        attr_done = 1;
    }

    kA<<<BB + 512, 256>>>(mask, ms, Wq);
    launch_pdl(kB, dim3(BB * SS + NH * 16), dim3(256), 0, H, Wk);
    launch_pdl(k_scores, dim3(SS / 128, BB, 4), dim3(256), 4 * SC_STAGE_B);
    launch_pdl(k_softmax, dim3(BB * NH), dim3(1024), 0);
    launch_pdl(k_agg, dim3(HID / 128, BB, 2), dim3(256), 4 * AG_STAGE_B);
    launch_pdl(k_mid, dim3(HEADS, BB, 4), dim3(256), 0, Wv);
    launch_pdl(k_final, dim3(HID / 64), dim3(512), 0, Wo, out);
}

// round 16
// speedup vs baseline: 1.0239x; 1.0239x over previous
#include <cuda_runtime.h>
#include <cuda_fp16.h>
#include <float.h>
#include <stdint.h>

#define HID 4096
#define SLOTS 8
#define HEADS 8
#define BD 512
#define HD 64
#define BB 4
#define SS 4096
#define NH 64   // HEADS*SLOTS

// Scratch (no allocations allowed)
__device__ float  g_Q[SLOTS * BD];
__device__ __half g_Qk16[NH * HID];              // fp16, scaled by 1/8
__device__ __half g_H16c[(size_t)BB * SS * HID]; // fp16 H, compacted rows
__device__ __half g_spart16[4 * BB * NH * SS];   // split-K score partials (fp16)
__device__ __half g_attnh[BB * NH * SS];         // attn probs (fp16)
__device__ float  g_apart[2 * BB * NH * HID];    // split-s agg partials
__device__ float  g_mid[BB * SLOTS * BD];
__device__ int    g_sidx[BB * SS];
__device__ int    g_cnt[BB];

#define SPART_SZ (BB * NH * SS)
#define APART_SZ (BB * NH * HID)

__device__ __forceinline__ void mma_f16(float* d, const uint32_t* a, const uint32_t* b) {
    asm volatile(
        "mma.sync.aligned.m16n8k16.row.col.f32.f16.f16.f32 "
        "{%0,%1,%2,%3}, {%4,%5,%6,%7}, {%8,%9}, {%0,%1,%2,%3};"
        : "+f"(d[0]), "+f"(d[1]), "+f"(d[2]), "+f"(d[3])
        : "r"(a[0]), "r"(a[1]), "r"(a[2]), "r"(a[3]), "r"(b[0]), "r"(b[1]));
}

__device__ __forceinline__ void ldm_x4(uint32_t* r, uint32_t addr) {
    asm volatile(
        "ldmatrix.sync.aligned.m8n8.x4.shared.b16 {%0,%1,%2,%3}, [%4];"
        : "=r"(r[0]), "=r"(r[1]), "=r"(r[2]), "=r"(r[3]) : "r"(addr));
}

__device__ __forceinline__ void ldm_x4t(uint32_t* r, uint32_t addr) {
    asm volatile(
        "ldmatrix.sync.aligned.m8n8.x4.trans.shared.b16 {%0,%1,%2,%3}, [%4];"
        : "=r"(r[0]), "=r"(r[1]), "=r"(r[2]), "=r"(r[3]) : "r"(addr));
}

__device__ __forceinline__ void cp16(uint32_t smem_dst, const void* gsrc) {
    asm volatile("cp.async.cg.shared.global [%0], [%1], 16;" :: "r"(smem_dst), "l"(gsrc));
}
#define CP_COMMIT asm volatile("cp.async.commit_group;")
#define CP_WAIT2  asm volatile("cp.async.wait_group 2;")
#define CP_WAIT0  asm volatile("cp.async.wait_group 0;")

// ---------------------------------------------------------------------------
// A) HORIZONTAL FUSION: blocks [0,BB) compact+zero g_mid; blocks [BB,..) qproj
__global__ void kA(const int* __restrict__ mask,
                   const float* __restrict__ ms, const float* __restrict__ Wq) {
    int tid = threadIdx.x;
    if (blockIdx.x < BB) {
        __shared__ int tsum[256];
        int b = blockIdx.x;
        const int* m = mask + b * SS;
        int loc[16], cnt = 0;
        #pragma unroll
        for (int k = 0; k < 16; k++) {
            loc[k] = (m[tid * 16 + k] != 0);
            cnt += loc[k];
        }
        tsum[tid] = cnt;
        __syncthreads();
        for (int o = 1; o < 256; o <<= 1) {
            int v = (tid >= o) ? tsum[tid - o] : 0;
            __syncthreads();
            tsum[tid] += v;
            __syncthreads();
        }
        int off = tsum[tid] - cnt;
        int total = tsum[255];
        int* out = g_sidx + b * SS;
        #pragma unroll
        for (int k = 0; k < 16; k++)
            if (loc[k]) out[off++] = tid * 16 + k;
        if (tid == 0) g_cnt[b] = total;
        float* gm = g_mid + b * 4096;
        #pragma unroll
        for (int k = 0; k < 16; k++) gm[k * 256 + tid] = 0.f;
    } else {
        int warp = ((blockIdx.x - BB) * 256 + tid) >> 5;
        int lane = tid & 31;
        if (warp >= SLOTS * BD) return;
        int n = warp / BD, c = warp % BD;
        const float* a = ms + n * HID;
        const float* w = Wq + c * HID;
        float acc = 0.f;
        for (int i = lane; i < HID; i += 32) acc += a[i] * w[i];
        #pragma unroll
        for (int off = 16; off; off >>= 1) acc += __shfl_down_sync(0xffffffffu, acc, off);
        if (lane == 0) g_Q[n * BD + c] = acc;
    }
}

// ---------------------------------------------------------------------------
// B) HORIZONTAL FUSION: blocks [0, BB*SS) conv (1 row/block, pad 128); rest qk
__global__ void kB(const float* __restrict__ H, const float* __restrict__ Wk) {
    cudaGridDependencySynchronize();
    int tid = threadIdx.x;
    int blk = blockIdx.x;
    if (blk < BB * SS) {
        int b = blk >> 12, cs = blk & 4095;
        int cnt = g_cnt[b];
        if (cs < cnt) {
            int s = g_sidx[b * SS + cs];
            const float4* src = (const float4*)(H + ((size_t)b * SS + s) * HID);
            uint2* dst = (uint2*)(g_H16c + ((size_t)b * SS + cs) * HID);
            float4 v0 = src[tid];
            float4 v1 = src[256 + tid];
            float4 v2 = src[512 + tid];
            float4 v3 = src[768 + tid];
            __half2 a0 = __floats2half2_rn(v0.x, v0.y), a1 = __floats2half2_rn(v0.z, v0.w);
            __half2 b0 = __floats2half2_rn(v1.x, v1.y), b1 = __floats2half2_rn(v1.z, v1.w);
            __half2 c0 = __floats2half2_rn(v2.x, v2.y), c1 = __floats2half2_rn(v2.z, v2.w);
            __half2 d0 = __floats2half2_rn(v3.x, v3.y), d1 = __floats2half2_rn(v3.z, v3.w);
            uint2 p0 = make_uint2(*(uint32_t*)&a0, *(uint32_t*)&a1);
            uint2 p1 = make_uint2(*(uint32_t*)&b0, *(uint32_t*)&b1);
            uint2 p2 = make_uint2(*(uint32_t*)&c0, *(uint32_t*)&c1);
            uint2 p3 = make_uint2(*(uint32_t*)&d0, *(uint32_t*)&d1);
            dst[tid] = p0; dst[256 + tid] = p1; dst[512 + tid] = p2; dst[768 + tid] = p3;
        } else if (cs < cnt + 128) {
            uint2* dst = (uint2*)(g_H16c + ((size_t)b * SS + cs) * HID);
            uint2 z = make_uint2(0u, 0u);
            dst[tid] = z; dst[256 + tid] = z; dst[512 + tid] = z; dst[768 + tid] = z;
        }
    } else {
        __shared__ float qs[HD];
        int idx = blk - BB * SS;
        int j = idx >> 4;            // 0..63
        int chunk = idx & 15;
        int h = j >> 3, n = j & 7;
        if (tid < HD) qs[tid] = g_Q[n * BD + h * HD + tid];
        __syncthreads();
        int i = chunk * 256 + tid;
        float acc = 0.f;
        #pragma unroll 8
        for (int d = 0; d < HD; d++) acc += qs[d] * Wk[(h * HD + d) * HID + i];
        g_Qk16[j * HID + i] = __float2half(acc * 0.125f);
    }
}

// ---------------------------------------------------------------------------
// 3) scores fp16: tile 128cs x 64j, split-K x4, 4-stage cp.async, ldmatrix
#define SC_A_B (128 * 80)           // 10240 B
#define SC_B_B (64 * 80)            // 5120 B
#define SC_STAGE_B (SC_A_B + SC_B_B)// 15360 B
__global__ void __launch_bounds__(256) k_scores() {
    cudaGridDependencySynchronize();
    extern __shared__ char smc[];
    int b = blockIdx.y, m0 = blockIdx.x * 128, kc = blockIdx.z;
    int cnt = g_cnt[b];
    if (m0 >= cnt) return;
    int tid = threadIdx.x, lane = tid & 31, w = tid >> 5;
    int wm = w & 3, wn = w >> 2;       // 4 m-groups x 2 n-groups
    int R = wm * 32, C = wn * 32;
    int ar = lane >> 2, ac = lane & 3;
    uint32_t smem_u32 = (uint32_t)__cvta_generic_to_shared(smc);

    float acc[2][4][4];
    #pragma unroll
    for (int t = 0; t < 2; t++)
        #pragma unroll
        for (int n = 0; n < 4; n++)
            #pragma unroll
            for (int q = 0; q < 4; q++) acc[t][n][q] = 0.f;

    int arow = tid >> 2;               // 0..63
    int aseg = tid & 3;                // 0..3 x16B
    const __half* Asrc = g_H16c + ((size_t)b * SS + m0) * HID + kc * 1024;
    const __half* Bsrc = g_Qk16 + kc * 1024;

    auto issue = [&](int stage, int it) {
        int st = it * 32;
        uint32_t base = smem_u32 + stage * SC_STAGE_B;
        cp16(base + arow * 80 + aseg * 16, Asrc + (size_t)arow * HID + st + aseg * 8);
        cp16(base + (arow + 64) * 80 + aseg * 16,
             Asrc + (size_t)(arow + 64) * HID + st + aseg * 8);
        cp16(base + SC_A_B + arow * 80 + aseg * 16,
             Bsrc + (size_t)arow * HID + st + aseg * 8);
    };

    int lr16 = lane & 15;
    int lhi = lane >> 4;

    const int NIT = 32;
    issue(0, 0); CP_COMMIT;
    issue(1, 1); CP_COMMIT;
    issue(2, 2); CP_COMMIT;
    for (int it = 0; it < NIT; it++) {
        CP_WAIT2;
        __syncthreads();
        if (it + 3 < NIT) issue((it + 3) & 3, it + 3);
        CP_COMMIT;
        uint32_t abase = smem_u32 + (it & 3) * SC_STAGE_B;
        uint32_t bbase = abase + SC_A_B;
        #pragma unroll
        for (int ks = 0; ks < 2; ks++) {
            uint32_t colb = (uint32_t)(ks * 32 + lhi * 16);
            uint32_t a[2][4];
            #pragma unroll
            for (int t = 0; t < 2; t++)
                ldm_x4(a[t], abase + (uint32_t)((R + t * 16 + lr16) * 80) + colb);
            uint32_t rbA[4], rbB[4];
            ldm_x4(rbA, bbase + (uint32_t)((C + lr16) * 80) + colb);
            ldm_x4(rbB, bbase + (uint32_t)((C + 16 + lr16) * 80) + colb);
            uint32_t bf[4][2] = {{rbA[0], rbA[2]}, {rbA[1], rbA[3]},
                                 {rbB[0], rbB[2]}, {rbB[1], rbB[3]}};
            #pragma unroll
            for (int t = 0; t < 2; t++)
                #pragma unroll
                for (int n = 0; n < 4; n++)
                    mma_f16(acc[t][n], a[t], bf[n]);
        }
    }
    CP_WAIT0;
    __syncthreads();

    // transpose-stage C (128cs x 64j) -> g_spart16[kc][(b,j)][cs]
    float* Cs = (float*)smc;
    #pragma unroll
    for (int t = 0; t < 2; t++) {
        #pragma unroll
        for (int n = 0; n < 4; n++) {
            int row = R + t * 16 + ar;
            int col = C + n * 8 + 2 * ac;
            Cs[col * 130 + row]            = acc[t][n][0];
            Cs[(col + 1) * 130 + row]      = acc[t][n][1];
            Cs[col * 130 + row + 8]        = acc[t][n][2];
            Cs[(col + 1) * 130 + row + 8]  = acc[t][n][3];
        }
    }
    __syncthreads();
    __half* dst = g_spart16 + (size_t)kc * SPART_SZ;
    #pragma unroll
    for (int l = 0; l < 32; l++) {
        int e = l * 256 + tid;
        int j = e >> 7, m = e & 127;
        dst[((b * NH + j) << 12) + m0 + m] = __float2half(Cs[j * 130 + m]);
    }
}

// ---------------------------------------------------------------------------
// 4) softmax (256 thr): shuffle-reduce; sum 4 fp16 split-K partials
__global__ void __launch_bounds__(256) k_softmax() {
    cudaGridDependencySynchronize();
    __shared__ float red[8];
    int row = blockIdx.x;
    int b = row >> 6;
    int cnt = g_cnt[b];
    const __half* p0 = g_spart16 + (size_t)row * SS;
    __half* sc = g_attnh + (size_t)row * SS;
    int tid = threadIdx.x;
    int lane = tid & 31, wrp = tid >> 5;
    float v[16];
    float mx = -FLT_MAX;
    #pragma unroll
    for (int k = 0; k < 16; k++) {
        int s = k * 256 + tid;
        float val = -FLT_MAX;
        if (s < cnt)
            val = __half2float(p0[s]) + __half2float(p0[SPART_SZ + s])
                + __half2float(p0[2 * SPART_SZ + s]) + __half2float(p0[3 * SPART_SZ + s]);
        v[k] = val;
        mx = fmaxf(mx, val);
    }
    #pragma unroll
    for (int o = 16; o; o >>= 1) mx = fmaxf(mx, __shfl_xor_sync(0xffffffffu, mx, o));
    if (lane == 0) red[wrp] = mx;
    __syncthreads();
    mx = red[lane & 7];
    #pragma unroll
    for (int o = 4; o; o >>= 1) mx = fmaxf(mx, __shfl_xor_sync(0xffffffffu, mx, o));
    float sum = 0.f;
    #pragma unroll
    for (int k = 0; k < 16; k++) {
        int s = k * 256 + tid;
        v[k] = (s < cnt) ? __expf(v[k] - mx) : 0.f;
        sum += v[k];
    }
    #pragma unroll
    for (int o = 16; o; o >>= 1) sum += __shfl_xor_sync(0xffffffffu, sum, o);
    __syncthreads();
    if (lane == 0) red[wrp] = sum;
    __syncthreads();
    sum = red[lane & 7];
    #pragma unroll
    for (int o = 4; o; o >>= 1) sum += __shfl_xor_sync(0xffffffffu, sum, o);
    float inv = 1.f / sum;
    #pragma unroll
    for (int k = 0; k < 16; k++) sc[k * 256 + tid] = __float2half(v[k] * inv);
}

// ---------------------------------------------------------------------------
// 5) agg fp16: tile 64j x 128i, split-s x2, A via ldmatrix.x4,
//    B=H16c [s][i] via ldmatrix.x4.trans
#define AGA_B (64 * 80)              // 5120 B attn tile
#define AGB_STRIDE 272               // B row stride bytes (128 halves + 8 pad)
#define AGB_B (32 * AGB_STRIDE)      // 8704 B
#define AG_STAGE_B (AGA_B + AGB_B)   // 13824 B
__global__ void __launch_bounds__(256) k_agg() {
    cudaGridDependencySynchronize();
    extern __shared__ char smc[];
    int tid = threadIdx.x, lane = tid & 31, w = tid >> 5;
    int wm = w & 1, wn = w >> 1;       // 2 j-groups x 4 i-groups
    int R = wm * 32, C = wn * 32;
    int b = blockIdx.y;
    int i0 = blockIdx.x * 128;
    int sc_id = blockIdx.z;
    int ar = lane >> 2, ac = lane & 3;
    int cnt = g_cnt[b];
    int NIT_total = (cnt + 31) >> 5;
    int half = (NIT_total + 1) >> 1;
    int it0 = sc_id * half;
    int it1 = min(NIT_total, it0 + half);

    uint32_t smem_u32 = (uint32_t)__cvta_generic_to_shared(smc);

    float acc[2][4][4];
    #pragma unroll
    for (int t = 0; t < 2; t++)
        #pragma unroll
        for (int n = 0; n < 4; n++)
            #pragma unroll
            for (int q = 0; q < 4; q++) acc[t][n][q] = 0.f;

    const __half* Asrc = g_attnh + (size_t)b * NH * SS;
    const __half* Bsrc = g_H16c + (size_t)b * SS * HID + i0;

    int rrow = tid >> 2;               // 0..63 (attn rows)
    int rc8 = (tid & 3) * 8;
    int brow = tid >> 3;               // 0..31 (H rows)
    int bseg = tid & 7;                // 0..7

    auto issue = [&](int stage, int it) {
        int st = it * 32;
        uint32_t base = smem_u32 + stage * AG_STAGE_B;
        cp16(base + rrow * 80 + (tid & 3) * 16, Asrc + (size_t)rrow * SS + st + rc8);
        uint32_t bb = base + AGA_B + brow * AGB_STRIDE;
        const __half* hb = Bsrc + (size_t)(st + brow) * HID;
        cp16(bb + bseg * 16, hb + bseg * 8);
        cp16(bb + (bseg + 8) * 16, hb + (bseg + 8) * 8);
    };

    int lr16 = lane & 15;
    int lhi = lane >> 4;

    if (it0 < it1) {
        issue(0, it0); CP_COMMIT;
        if (it0 + 1 < it1) issue(1, it0 + 1); CP_COMMIT;
        if (it0 + 2 < it1) issue(2, it0 + 2); CP_COMMIT;
        for (int it = it0; it < it1; it++) {
            CP_WAIT2;
            __syncthreads();
            if (it + 3 < it1) issue((it - it0 + 3) & 3, it + 3);
            CP_COMMIT;
            int stg = (it - it0) & 3;
            uint32_t abase = smem_u32 + stg * AG_STAGE_B;
            uint32_t bbase = abase + AGA_B;
            #pragma unroll
            for (int ks = 0; ks < 2; ks++) {
                uint32_t colb = (uint32_t)(ks * 32 + lhi * 16);
                uint32_t a[2][4];
                #pragma unroll
                for (int t = 0; t < 2; t++)
                    ldm_x4(a[t], abase + (uint32_t)((R + t * 16 + lr16) * 80) + colb);
                uint32_t rowb = (uint32_t)((ks * 16 + lr16) * AGB_STRIDE);
                uint32_t rb0[4], rb1[4];
                ldm_x4t(rb0, bbase + rowb + (uint32_t)((C + lhi * 8) * 2));
                ldm_x4t(rb1, bbase + rowb + (uint32_t)((C + 16 + lhi * 8) * 2));
                uint32_t bf[4][2] = {{rb0[0], rb0[1]}, {rb0[2], rb0[3]},
                                     {rb1[0], rb1[1]}, {rb1[2], rb1[3]}};
                #pragma unroll
                for (int t = 0; t < 2; t++)
                    #pragma unroll
                    for (int n = 0; n < 4; n++)
                        mma_f16(acc[t][n], a[t], bf[n]);
            }
        }
    }

    float* dst = g_apart + sc_id * APART_SZ;
    #pragma unroll
    for (int t = 0; t < 2; t++) {
        #pragma unroll
        for (int n = 0; n < 4; n++) {
            int j = R + t * 16 + ar;
            int i = C + n * 8 + 2 * ac;
            float2 v0 = make_float2(acc[t][n][0], acc[t][n][1]);
            float2 v1 = make_float2(acc[t][n][2], acc[t][n][3]);
            *(float2*)&dst[(size_t)(b * NH + j) * HID + i0 + i]     = v0;
            *(float2*)&dst[(size_t)(b * NH + j + 8) * HID + i0 + i] = v1;
        }
    }
}

// ---------------------------------------------------------------------------
// 6) mid, split-K x4 with atomic epilogue; sums the 2 agg partials
__global__ void k_mid(const float* __restrict__ Wv) {
    cudaGridDependencySynchronize();
    __shared__ float As[8][65];
    __shared__ float Bs[64][65];
    int h = blockIdx.x, b = blockIdx.y, kc = blockIdx.z;
    int tid = threadIdx.x;
    float acc0 = 0.f, acc1 = 0.f;
    int o0 = tid, o1 = tid + 256;
    int n0 = o0 >> 6, d0 = o0 & 63;
    int n1 = o1 >> 6, d1 = o1 & 63;
    int k0 = kc * (HID / 4), k1 = k0 + HID / 4;
    for (int kt = k0; kt < k1; kt += 64) {
        {
            int e = tid; int r = e >> 6, c = e & 63;
            size_t ix = (size_t)(b * NH + h * SLOTS + r) * HID + kt + c;
            As[r][c] = g_apart[ix] + g_apart[APART_SZ + ix];
            e = tid + 256; r = e >> 6; c = e & 63;
            ix = (size_t)(b * NH + h * SLOTS + r) * HID + kt + c;
            As[r][c] = g_apart[ix] + g_apart[APART_SZ + ix];
        }
        #pragma unroll
        for (int l = 0; l < 16; l++) {
            int e = tid + l * 256;
            int r = e >> 6, c = e & 63;
            Bs[r][c] = Wv[(h * HD + r) * HID + kt + c];
        }
        __syncthreads();
        #pragma unroll
        for (int k = 0; k < 64; k++) {
            acc0 += As[n0][k] * Bs[d0][k];
            acc1 += As[n1][k] * Bs[d1][k];
        }
        __syncthreads();
    }
    atomicAdd(&g_mid[(b * SLOTS + n0) * BD + h * HD + d0], acc0);
    atomicAdd(&g_mid[(b * SLOTS + n1) * BD + h * HD + d1], acc1);
}

// ---------------------------------------------------------------------------
// 7) final, o-tile 64, 512 threads
__global__ void __launch_bounds__(512) k_final(const float* __restrict__ Wo,
                                               float* __restrict__ out) {
    cudaGridDependencySynchronize();
    __shared__ float As[32][65];
    __shared__ float Bs[64][65];
    int tid = threadIdx.x;
    int tx = tid & 15, ty = tid >> 4;      // 16 col-groups x 32 rows
    int o0 = blockIdx.x * 64;
    float acc[4] = {};
    for (int kt = 0; kt < BD; kt += 64) {
        #pragma unroll
        for (int l = 0; l < 4; l++) {
            int e = tid + l * 512;
            int r = e >> 6, c = e & 63;
            As[r][c] = g_mid[r * BD + kt + c];
        }
        #pragma unroll
        for (int l = 0; l < 8; l++) {
            int e = tid + l * 512;
            int r = e >> 6, c = e & 63;
            Bs[r][c] = Wo[(o0 + r) * BD + kt + c];
        }
        __syncthreads();
        #pragma unroll
        for (int k = 0; k < 64; k++) {
            float a = As[ty][k];
            #pragma unroll
            for (int y = 0; y < 4; y++) acc[y] += a * Bs[tx * 4 + y][k];
        }
        __syncthreads();
    }
    #pragma unroll
    for (int y = 0; y < 4; y++)
        out[ty * HID + o0 + tx * 4 + y] = acc[y];
}

// ---------------------------------------------------------------------------
template <typename K, typename... Args>
static void launch_pdl(K kern, dim3 grid, dim3 block, size_t smem, Args... args) {
    cudaLaunchConfig_t cfg = {};
    cfg.gridDim = grid;
    cfg.blockDim = block;
    cfg.dynamicSmemBytes = smem;
    cudaLaunchAttribute at[1];
    at[0].id = cudaLaunchAttributeProgrammaticStreamSerialization;
    at[0].val.programmaticStreamSerializationAllowed = 1;
    cfg.attrs = at;
    cfg.numAttrs = 1;
    cudaLaunchKernelEx(&cfg, kern, args...);
}

extern "C" void kernel_launch(void* const* d_in, const int* in_sizes, int n_in,
                              void* d_out, int out_size) {
    const float* H    = (const float*)d_in[0];
    const int*   mask = (const int*)d_in[1];
    const float* ms   = (const float*)d_in[2];
    const float* Wq   = (const float*)d_in[3];
    const float* Wk   = (const float*)d_in[4];
    const float* Wv   = (const float*)d_in[5];
    const float* Wo   = (const float*)d_in[6];
    float* out = (float*)d_out;

    static int attr_done = 0;
    if (!attr_done) {
        cudaFuncSetAttribute(k_scores, cudaFuncAttributeMaxDynamicSharedMemorySize,
                             4 * SC_STAGE_B);
        cudaFuncSetAttribute(k_agg, cudaFuncAttributeMaxDynamicSharedMemorySize,
                             4 * AG_STAGE_B);
        attr_done = 1;
    }

    kA<<<BB + 512, 256>>>(mask, ms, Wq);
    launch_pdl(kB, dim3(BB * SS + NH * 16), dim3(256), 0, H, Wk);
    launch_pdl(k_scores, dim3(SS / 128, BB, 4), dim3(256), 4 * SC_STAGE_B);
    launch_pdl(k_softmax, dim3(BB * NH), dim3(256), 0);
    launch_pdl(k_agg, dim3(HID / 128, BB, 2), dim3(256), 4 * AG_STAGE_B);
    launch_pdl(k_mid, dim3(HEADS, BB, 4), dim3(256), 0, Wv);
    launch_pdl(k_final, dim3(HID / 64), dim3(512), 0, Wo, out);
}